// round 13
// baseline (speedup 1.0000x reference)
#include <cuda_runtime.h>
#include <math.h>
#include <stdint.h>

// Problem dims
#define Bk 64
#define Tk 256
#define Dk 512
#define Hk 1024
#define Gk 3072   // 3*H
#define Ok 64
#define BT 16384  // B*T

#define NB 128    // persistent blocks, one per 8 h-columns; all co-resident (1/SM)

typedef unsigned long long ull;

// -------- device scratch (no allocation allowed; __device__ globals are the workaround)
__device__ float g_gates[(long)BT * Gk];      // [T][B][3H]  (201 MB)
__device__ float g_hsT[(long)Tk * Hk * Bk];   // [t][k][b] transposed h (64 MB)

__device__ unsigned g_bar_count;                  // init barrier: returns to 0 each use
__device__ volatile unsigned g_bar_gen;           // init barrier: monotonic (replay-safe)
__device__ __align__(16) unsigned g_flags[NB];    // dataflow: block b done through step s-1

// -------- packed f32x2 helpers (Blackwell FFMA2: 2x fp32 FMA throughput, exact fp32)
__device__ __forceinline__ ull ffma2(ull a, ull b, ull c) {
  ull d;
  asm("fma.rn.f32x2 %0, %1, %2, %3;" : "=l"(d) : "l"(a), "l"(b), "l"(c));
  return d;
}
__device__ __forceinline__ ull pack2(float lo, float hi) {
  ull d; asm("mov.b64 %0, {%1, %2};" : "=l"(d) : "f"(lo), "f"(hi)); return d;
}
__device__ __forceinline__ float2 unpack2(ull v) {
  float2 r; asm("mov.b64 {%0, %1}, %2;" : "=f"(r.x), "=f"(r.y) : "l"(v)); return r;
}
__device__ __forceinline__ float sigmoidf_(float x) { return 1.0f / (1.0f + expf(-x)); }

// -------- cp.async (LDGSTS via L2: .cg — no L1 staleness issues)
__device__ __forceinline__ void cp16(uint32_t dst, const float* src) {
  asm volatile("cp.async.cg.shared.global [%0], [%1], 16;" :: "r"(dst), "l"(src));
}
__device__ __forceinline__ void cp_commit() { asm volatile("cp.async.commit_group;"); }
__device__ __forceinline__ void cp_wait0()  { asm volatile("cp.async.wait_group 0;"); }

// -------- dataflow flags: STRONG scoped ops (morally-strong release/acquire).
// Round-12 used weak .cg/.cv ops — the PTX memory model gives weak pairs NO
// synchronizes-with edge, so the flag could become visible before the h data
// it released (observed as stale-h races). st.release.gpu is cumulative over
// the __syncthreads() happens-before; ld.relaxed.gpu + __threadfence() is a
// valid acquire of it.
__device__ __forceinline__ unsigned ld_relaxed(const unsigned* p) {
  unsigned v;
  asm volatile("ld.relaxed.gpu.global.u32 %0, [%1];" : "=r"(v) : "l"(p) : "memory");
  return v;
}
__device__ __forceinline__ void st_release(unsigned* p, unsigned v) {
  asm volatile("st.release.gpu.global.u32 [%0], %1;" :: "l"(p), "r"(v) : "memory");
}
__device__ __forceinline__ void wait_chunk(const unsigned* p, unsigned t) {
  while (ld_relaxed(p + 0) < t || ld_relaxed(p + 1) < t ||
         ld_relaxed(p + 2) < t || ld_relaxed(p + 3) < t) { }
  __threadfence();   // acquire upgrade: orders subsequent data reads
}

// ============================================================================
// Kernel 1: gates_x = gather(emb, x) @ W_ih^T + b_ih   (M=16384 N=3072 K=512)
//   Tile 128x128x32, 256 thr, per-thread 8 rows (4 adjacent pairs) x 8 cols.
//   Inner loop: A 4xLDS.64 (upper half-warp broadcasts), B 4xLDS.128 ->
//   crossbar/fma ~0.4. Each output keeps its own ascending-k FFMA chain.
// ============================================================================
__global__ __launch_bounds__(256) void gates_kernel(
    const int* __restrict__ x, const float* __restrict__ emb,
    const float* __restrict__ W_ih, const float* __restrict__ b_ih) {
  extern __shared__ char gsm[];
  float* Xs  = (float*)gsm;                       // [32 k][130] floats (pad)
  ull*   Wsd = (ull*)(gsm + 16640);               // [32 k][132] dup f32x2 (pad)
  int*   toks = (int*)(gsm + 16640 + 33792);      // [128]

  const int tid = threadIdx.x;
  const int r0 = blockIdx.x * 128;
  const int c0 = blockIdx.y * 128;

  if (tid < 128) {
    int r = r0 + tid;
    toks[tid] = x[(r & 63) * Tk + (r >> 6)];  // b = r&63, t = r>>6
  }
  __syncthreads();

  ull acc[4][8] = {};                 // 4 adjacent-row pairs x 8 cols
  const int l16 = tid & 15;
  const int cg  = tid >> 4;           // 16 col-groups x 8 cols
  const int f4 = tid & 7;             // fill: float4 index within 32-float chunk
  const int rw = tid >> 3;            // fill: base row 0..31

  for (int kc = 0; kc < Dk; kc += 32) {
    // ---- A fill: 128 rows x 8 f4; per warp 4 rows x 8 f4 = 4 lines
#pragma unroll
    for (int i = 0; i < 4; i++) {
      int row = rw + i * 32;
      float4 v = *reinterpret_cast<const float4*>(
          &emb[(long)toks[row] * Dk + kc + f4 * 4]);
      Xs[(f4 * 4 + 0) * 130 + row] = v.x;
      Xs[(f4 * 4 + 1) * 130 + row] = v.y;
      Xs[(f4 * 4 + 2) * 130 + row] = v.z;
      Xs[(f4 * 4 + 3) * 130 + row] = v.w;
    }
    // ---- W fill (duplicated f32x2): 128 cols x 8 f4; 4 lines/warp
#pragma unroll
    for (int i = 0; i < 4; i++) {
      int n = rw + i * 32;
      float4 v = *reinterpret_cast<const float4*>(
          &W_ih[(long)(c0 + n) * Dk + kc + f4 * 4]);
      Wsd[(f4 * 4 + 0) * 132 + n] = pack2(v.x, v.x);
      Wsd[(f4 * 4 + 1) * 132 + n] = pack2(v.y, v.y);
      Wsd[(f4 * 4 + 2) * 132 + n] = pack2(v.z, v.z);
      Wsd[(f4 * 4 + 3) * 132 + n] = pack2(v.w, v.w);
    }
    __syncthreads();

#pragma unroll
    for (int k = 0; k < 32; k++) {
      ull av[4];
#pragma unroll
      for (int i = 0; i < 4; i++)
        av[i] = *reinterpret_cast<const ull*>(&Xs[k * 130 + 2 * (l16 + 16 * i)]);
      const ull* bp = &Wsd[k * 132 + cg * 8];
      ull bb[8];
#pragma unroll
      for (int u = 0; u < 4; u++) {
        ulonglong2 w = *reinterpret_cast<const ulonglong2*>(bp + 2 * u);
        bb[2 * u] = w.x; bb[2 * u + 1] = w.y;
      }
#pragma unroll
      for (int i = 0; i < 4; i++)
#pragma unroll
        for (int j = 0; j < 8; j++)
          acc[i][j] = ffma2(av[i], bb[j], acc[i][j]);
    }
    __syncthreads();
  }

  float bs[8];
#pragma unroll
  for (int j = 0; j < 8; j++) bs[j] = b_ih[c0 + cg * 8 + j];
#pragma unroll
  for (int i = 0; i < 4; i++) {
    float2 u[8];
#pragma unroll
    for (int j = 0; j < 8; j++) u[j] = unpack2(acc[i][j]);
    long rowa = (long)(r0 + 2 * (l16 + 16 * i)) * Gk + c0 + cg * 8;   // row 2m
    float4 lo0 = make_float4(u[0].x + bs[0], u[1].x + bs[1], u[2].x + bs[2], u[3].x + bs[3]);
    float4 lo1 = make_float4(u[4].x + bs[4], u[5].x + bs[5], u[6].x + bs[6], u[7].x + bs[7]);
    float4 hi0 = make_float4(u[0].y + bs[0], u[1].y + bs[1], u[2].y + bs[2], u[3].y + bs[3]);
    float4 hi1 = make_float4(u[4].y + bs[4], u[5].y + bs[5], u[6].y + bs[6], u[7].y + bs[7]);
    *reinterpret_cast<float4*>(&g_gates[rowa]) = lo0;
    *reinterpret_cast<float4*>(&g_gates[rowa + 4]) = lo1;
    *reinterpret_cast<float4*>(&g_gates[rowa + Gk]) = hi0;       // row 2m+1
    *reinterpret_cast<float4*>(&g_gates[rowa + Gk + 4]) = hi1;
  }
}

// ============================================================================
// init_bar: generation-relative atomic barrier (replay-safe). Used ONCE at
// kernel entry to publish the flag resets.
// ============================================================================
__device__ __forceinline__ void init_bar() {
  __threadfence();
  __syncthreads();
  if (threadIdx.x == 0) {
    unsigned my = g_bar_gen;
    if (atomicAdd(&g_bar_count, 1u) == NB - 1) {
      g_bar_count = 0;
      __threadfence();
      g_bar_gen = my + 1;
    } else {
      while (g_bar_gen == my) { }
      __threadfence();
    }
  }
  __syncthreads();
}

// ============================================================================
// Persistent GRU recurrence — NO grid barrier. Producer/consumer dataflow:
//   chunk (q,i) of the h(t-1) A-tile needs exactly blocks q*32+i*4+{0..3};
//   each block release-publishes flag=t+1 after writing its h(t) columns.
//   Waits hide under the previous chunk's compute; g_hsT is indexed by t so
//   there is no WAR hazard. Accumulation order bit-identical to all passing
//   versions (4 k-quarter chains, smem left-fold s=0..3, same gate exprs).
// ============================================================================
__global__ __launch_bounds__(256, 1) void gru_persistent(
    const float* __restrict__ W_hh, const float* __restrict__ b_hh) {
  extern __shared__ float smem[];
  float* Ws    = smem;                 // [1024 k][24 rows]          96 KB
  float* HsBuf = smem + 24576;         // [2 buf][4 q][32 k][64 b]   64 KB
  float* P     = HsBuf + 16384;        // [4 s][64 b][26 pad]        26 KB
  float* Hprev = P + 6656;             // [64 b][8 jl]                2 KB

  const int tid = threadIdx.x;
  const int g = blockIdx.x;            // 0..127: h-cols g*8..g*8+7
  const int q = tid >> 6;              // k-quarter 0..3
  const int l = tid & 63;
  const int m0 = (l & 15) << 2;        // 4 batch rows
  const int n0 = (l >> 4) * 6;         // 6 local cols = 3 f32x2 pairs
  const int jl = tid & 7;              // gate-stage: local h-col
  const int b0 = tid >> 3;             // gate-stage: batch (and b0+32)

  // ---- reset dataflow flags (persist across graph replays), then publish
  if (g == 0 && tid < NB) st_release(&g_flags[tid], 0u);

  // ---- load W slice once: local row L = e*8+c  ->  W_hh row e*1024+g*8+c
  for (int i = tid; i < 24 * 256; i += 256) {
    int L = i >> 8;
    int f4 = i & 255;
    int e = L >> 3, c = L & 7;
    float4 v = *reinterpret_cast<const float4*>(
        &W_hh[(long)(e * Hk + g * 8 + c) * Hk + f4 * 4]);
    int kk = f4 * 4;
    Ws[(kk + 0) * 24 + L] = v.x;
    Ws[(kk + 1) * 24 + L] = v.y;
    Ws[(kk + 2) * 24 + L] = v.z;
    Ws[(kk + 3) * 24 + L] = v.w;
  }
  const float bh0 = b_hh[g * 8 + jl];
  const float bh1 = b_hh[Hk + g * 8 + jl];
  const float bh2 = b_hh[2 * Hk + g * 8 + jl];

  init_bar();   // flag resets visible everywhere before any producer publish
  __syncthreads();

  const uint32_t hsbuf_s = (uint32_t)__cvta_generic_to_shared(HsBuf);

  for (int t = 0; t < Tk; t++) {
    // ---- prefetch gx for this step's gate stage (hidden under the GEMM)
    float ga0, ga1, ga2, gb0, gb1, gb2;
    {
      const float* p0 = &g_gates[(long)(t * 64 + b0) * Gk + g * 8 + jl];
      ga0 = p0[0]; ga1 = p0[Hk]; ga2 = p0[2 * Hk];
      const float* p1 = &g_gates[(long)(t * 64 + b0 + 32) * Gk + g * 8 + jl];
      gb0 = p1[0]; gb1 = p1[Hk]; gb2 = p1[2 * Hk];
    }

    if (t > 0) {
      const float* src = g_hsT + (long)(t - 1) * (Hk * Bk) + q * 256 * 64;
      {  // prologue: acquire producers of chunk 0, then issue into buffer 0
        wait_chunk(g_flags + q * 32, (unsigned)t);
        uint32_t dst = hsbuf_s + (uint32_t)((0 * 4 + q) * 2048 + l * 4) * 4;
        const float* s0 = src + l * 4;
#pragma unroll
        for (int j = 0; j < 8; j++) cp16(dst + j * 1024, s0 + j * 256);
        cp_commit();
      }

      ull acc[4][3] = {};
#pragma unroll 1
      for (int i = 0; i < 8; i++) {
        cp_wait0();
        __syncthreads();   // chunk i resident; everyone done with prior GEMM
        if (i < 7) {       // acquire producers of chunk i+1, issue into other buf
          wait_chunk(g_flags + q * 32 + (i + 1) * 4, (unsigned)t);
          int bf = (i + 1) & 1;
          uint32_t dst = hsbuf_s + (uint32_t)((bf * 4 + q) * 2048 + l * 4) * 4;
          const float* s1 = src + (i + 1) * 2048 + l * 4;
#pragma unroll
          for (int j = 0; j < 8; j++) cp16(dst + j * 1024, s1 + j * 256);
          cp_commit();
        }
        const float* A = HsBuf + ((i & 1) * 4 + q) * 2048;
        const float* Bw = Ws + (q * 256 + i * 32) * 24;
#pragma unroll
        for (int kk = 0; kk < 32; kk++) {
          float4 av = *reinterpret_cast<const float4*>(&A[kk * 64 + m0]);
          const float* wr = &Bw[kk * 24 + n0];
          ull w0 = *reinterpret_cast<const ull*>(wr);
          ull w1 = *reinterpret_cast<const ull*>(wr + 2);
          ull w2 = *reinterpret_cast<const ull*>(wr + 4);
          ull a0 = pack2(av.x, av.x), a1 = pack2(av.y, av.y);
          ull a2 = pack2(av.z, av.z), a3 = pack2(av.w, av.w);
          acc[0][0] = ffma2(a0, w0, acc[0][0]);
          acc[0][1] = ffma2(a0, w1, acc[0][1]);
          acc[0][2] = ffma2(a0, w2, acc[0][2]);
          acc[1][0] = ffma2(a1, w0, acc[1][0]);
          acc[1][1] = ffma2(a1, w1, acc[1][1]);
          acc[1][2] = ffma2(a1, w2, acc[1][2]);
          acc[2][0] = ffma2(a2, w0, acc[2][0]);
          acc[2][1] = ffma2(a2, w1, acc[2][1]);
          acc[2][2] = ffma2(a2, w2, acc[2][2]);
          acc[3][0] = ffma2(a3, w0, acc[3][0]);
          acc[3][1] = ffma2(a3, w1, acc[3][1]);
          acc[3][2] = ffma2(a3, w2, acc[3][2]);
        }
      }

      // ---- quarter partials -> smem (stride 26: bank-spread, 8B aligned)
#pragma unroll
      for (int m = 0; m < 4; m++) {
        int bb = m0 + m;
        float* pp = &P[(q * 64 + bb) * 26 + n0];
#pragma unroll
        for (int p = 0; p < 3; p++)
          *reinterpret_cast<float2*>(pp + 2 * p) = unpack2(acc[m][p]);
      }
      __syncthreads();
    }

    // ---- gate stage: 2 outputs per thread (b0, jl) and (b0+32, jl)
#pragma unroll
    for (int r2 = 0; r2 < 2; r2++) {
      int bb = b0 + r2 * 32;
      float gx0 = r2 ? gb0 : ga0;
      float gx1 = r2 ? gb1 : ga1;
      float gx2 = r2 ? gb2 : ga2;
      float hr = 0.0f, hz = 0.0f, hn = 0.0f;
      if (t > 0) {
#pragma unroll
        for (int s = 0; s < 4; s++) {   // left fold s=0..3: identical order
          const float* pp = &P[(s * 64 + bb) * 26];
          hr += pp[jl];
          hz += pp[8 + jl];
          hn += pp[16 + jl];
        }
      }
      float rr = sigmoidf_(gx0 + hr + bh0);
      float zz = sigmoidf_(gx1 + hz + bh1);
      float nn = tanhf(gx2 + rr * (hn + bh2));
      float hp = (t == 0) ? 0.0f : Hprev[bb * 8 + jl];
      float hnew = (1.0f - zz) * nn + zz * hp;
      Hprev[bb * 8 + jl] = hnew;                               // own slot
      g_hsT[(long)t * (Hk * Bk) + (g * 8 + jl) * 64 + bb] = hnew;
    }

    // ---- release-publish: h(t) for this block's 8 columns (cumulative over
    // the __syncthreads() happens-before from all 256 threads' stores)
    __syncthreads();
    if (tid == 0) st_release(&g_flags[g], (unsigned)(t + 1));
  }
}

// ============================================================================
// Kernel 4: logits = hs @ W_fc^T + b_fc; sigmoid; labels. One block per t.
//   Reads transposed h. label = (computed fp32 proba > 0.5f) — matches the
//   reference's sigmoid-then-compare rounding exactly.
// ============================================================================
__global__ __launch_bounds__(256) void fc_kernel(const float* __restrict__ W_fc,
                                                 const float* __restrict__ b_fc,
                                                 float* __restrict__ out,
                                                 int write_labels) {
  __shared__ __align__(16) float Hs[32][64];
  __shared__ __align__(16) float Ws[32][64];

  const int t = blockIdx.x;
  const int tid = threadIdx.x;
  const float* __restrict__ hbT = g_hsT + (long)t * (Hk * Bk);

  ull acc[2][4] = {};
  const int m0 = (tid & 15) * 4;
  const int n0 = (tid >> 4) * 4;
  const int kr = tid >> 4, f4i = tid & 15;

  for (int kc = 0; kc < Hk; kc += 32) {
#pragma unroll
    for (int u = 0; u < 2; u++) {
      int kk = kr + u * 16;
      float4 v = *reinterpret_cast<const float4*>(&hbT[(long)(kc + kk) * 64 + f4i * 4]);
      *reinterpret_cast<float4*>(&Hs[kk][f4i * 4]) = v;
    }
#pragma unroll
    for (int i = 0; i < 2; i++) {
      int n = (tid >> 3) + i * 32;         // warp-coalesced: 4 rows x 8 f4
      int f4 = tid & 7;
      float4 w = *reinterpret_cast<const float4*>(&W_fc[(long)n * Hk + kc + f4 * 4]);
      Ws[f4 * 4 + 0][n] = w.x; Ws[f4 * 4 + 1][n] = w.y;
      Ws[f4 * 4 + 2][n] = w.z; Ws[f4 * 4 + 3][n] = w.w;
    }
    __syncthreads();

#pragma unroll
    for (int k = 0; k < 32; k++) {
      const ull* ap = reinterpret_cast<const ull*>(&Hs[k][m0]);
      ull a0 = ap[0], a1 = ap[1];
      float4 bv = *reinterpret_cast<const float4*>(&Ws[k][n0]);
      ull bb[4];
      bb[0] = pack2(bv.x, bv.x); bb[1] = pack2(bv.y, bv.y);
      bb[2] = pack2(bv.z, bv.z); bb[3] = pack2(bv.w, bv.w);
#pragma unroll
      for (int j = 0; j < 4; j++) {
        acc[0][j] = ffma2(a0, bb[j], acc[0][j]);
        acc[1][j] = ffma2(a1, bb[j], acc[1][j]);
      }
    }
    __syncthreads();
  }

  const float bs0 = b_fc[n0 + 0], bs1 = b_fc[n0 + 1];
  const float bs2 = b_fc[n0 + 2], bs3 = b_fc[n0 + 3];
#pragma unroll
  for (int i = 0; i < 2; i++) {
    float2 u0 = unpack2(acc[i][0]), u1 = unpack2(acc[i][1]);
    float2 u2 = unpack2(acc[i][2]), u3 = unpack2(acc[i][3]);
    float lg[2][4] = {
        {u0.x + bs0, u1.x + bs1, u2.x + bs2, u3.x + bs3},
        {u0.y + bs0, u1.y + bs1, u2.y + bs2, u3.y + bs3}};
#pragma unroll
    for (int p = 0; p < 2; p++) {
      int b = m0 + 2 * i + p;
      long base = ((long)b * Tk + t) * Ok + n0;
      float4 pr = make_float4(sigmoidf_(lg[p][0]), sigmoidf_(lg[p][1]),
                              sigmoidf_(lg[p][2]), sigmoidf_(lg[p][3]));
      *reinterpret_cast<float4*>(&out[base]) = pr;
      if (write_labels) {
        float4 lb = make_float4(pr.x > 0.5f ? 1.0f : 0.0f,
                                pr.y > 0.5f ? 1.0f : 0.0f,
                                pr.z > 0.5f ? 1.0f : 0.0f,
                                pr.w > 0.5f ? 1.0f : 0.0f);
        *reinterpret_cast<float4*>(&out[(long)BT * Ok + base]) = lb;
      }
    }
  }
}

// ============================================================================
// Launch: graph-capturable (kernel launches only, deterministic, no allocs)
// ============================================================================
extern "C" void kernel_launch(void* const* d_in, const int* in_sizes, int n_in,
                              void* d_out, int out_size) {
  const int*   x    = (const int*)d_in[0];
  const float* emb  = (const float*)d_in[1];
  const float* W_ih = (const float*)d_in[2];
  const float* W_hh = (const float*)d_in[3];
  const float* b_ih = (const float*)d_in[4];
  const float* b_hh = (const float*)d_in[5];
  const float* W_fc = (const float*)d_in[6];
  const float* b_fc = (const float*)d_in[7];
  float* out = (float*)d_out;

  const int gsm_bytes = 16640 + 33792 + 512;                            // 51 KB
  cudaFuncSetAttribute(gates_kernel,
                       cudaFuncAttributeMaxDynamicSharedMemorySize, gsm_bytes);
  const int smem_bytes = (24576 + 16384 + 6656 + 512) * (int)sizeof(float); // 188 KB
  cudaFuncSetAttribute(gru_persistent,
                       cudaFuncAttributeMaxDynamicSharedMemorySize, smem_bytes);

  gates_kernel<<<dim3(128, 24), 256, gsm_bytes>>>(x, emb, W_ih, b_ih);
  gru_persistent<<<NB, 256, smem_bytes>>>(W_hh, b_hh);

  const int write_labels = (out_size >= 2 * BT * Ok) ? 1 : 0;
  fc_kernel<<<256, 256>>>(W_fc, b_fc, out, write_labels);
}

// round 14
// speedup vs baseline: 1.2614x; 1.2614x over previous
#include <cuda_runtime.h>
#include <math.h>
#include <stdint.h>

// Problem dims
#define Bk 64
#define Tk 256
#define Dk 512
#define Hk 1024
#define Gk 3072   // 3*H
#define Ok 64
#define BT 16384  // B*T

#define NB 128    // persistent blocks, one per 8 h-columns; all co-resident (1/SM)

typedef unsigned long long ull;

// -------- device scratch (no allocation allowed; __device__ globals are the workaround)
__device__ float g_gates[(long)BT * Gk];      // [T][B][3H]  (201 MB)
__device__ float g_hsT[(long)Tk * Hk * Bk];   // [t][k][b] transposed h (64 MB)

__device__ unsigned g_bar_count;                  // init barrier: returns to 0 each use
__device__ volatile unsigned g_bar_gen;           // init barrier: monotonic (replay-safe)
__device__ __align__(16) unsigned g_flags[NB];    // dataflow: block b done through step s-1

// -------- packed f32x2 helpers (Blackwell FFMA2: 2x fp32 FMA throughput, exact fp32)
__device__ __forceinline__ ull ffma2(ull a, ull b, ull c) {
  ull d;
  asm("fma.rn.f32x2 %0, %1, %2, %3;" : "=l"(d) : "l"(a), "l"(b), "l"(c));
  return d;
}
__device__ __forceinline__ ull pack2(float lo, float hi) {
  ull d; asm("mov.b64 %0, {%1, %2};" : "=l"(d) : "f"(lo), "f"(hi)); return d;
}
__device__ __forceinline__ float2 unpack2(ull v) {
  float2 r; asm("mov.b64 {%0, %1}, %2;" : "=f"(r.x), "=f"(r.y) : "l"(v)); return r;
}
__device__ __forceinline__ float sigmoidf_(float x) { return 1.0f / (1.0f + expf(-x)); }

// -------- cp.async (LDGSTS via L2: .cg — no L1 staleness issues)
__device__ __forceinline__ void cp16(uint32_t dst, const float* src) {
  asm volatile("cp.async.cg.shared.global [%0], [%1], 16;" :: "r"(dst), "l"(src));
}
__device__ __forceinline__ void cp_commit() { asm volatile("cp.async.commit_group;"); }
__device__ __forceinline__ void cp_wait0()  { asm volatile("cp.async.wait_group 0;"); }

// -------- dataflow flags: STRONG scoped ops (proved correct in round 13).
// st.release.gpu is cumulative over the block's __syncthreads() happens-before;
// ld.relaxed.gpu + __threadfence() acquires it. This round restricts polling
// to 16 threads/block (round 13 had all 256 spinning + fencing -> L2 spin-storm,
// step time doubled).
__device__ __forceinline__ unsigned ld_relaxed(const unsigned* p) {
  unsigned v;
  asm volatile("ld.relaxed.gpu.global.u32 %0, [%1];" : "=r"(v) : "l"(p) : "memory");
  return v;
}
__device__ __forceinline__ void st_release(unsigned* p, unsigned v) {
  asm volatile("st.release.gpu.global.u32 [%0], %1;" :: "l"(p), "r"(v) : "memory");
}
__device__ __forceinline__ void wait_one(const unsigned* p, unsigned t) {
  while (ld_relaxed(p) < t) { }
  __threadfence();   // acquire upgrade; propagated block-wide by next __syncthreads
}

// ============================================================================
// Kernel 1 (round-11 verbatim — measured best: fma 49.4%, occ 37%):
//   gates_x = gather(emb, x) @ W_ih^T + b_ih   (M=16384 N=3072 K=512)
//   Tile 128x64x32, warp-coalesced fills (4 rows x 8 f4 = 4 lines/warp),
//   adjacent-row pairing via even-offset LDS.64 (conflict-free).
// ============================================================================
__global__ __launch_bounds__(256) void gates_kernel(
    const int* __restrict__ x, const float* __restrict__ emb,
    const float* __restrict__ W_ih, const float* __restrict__ b_ih) {
  __shared__ __align__(16) float Xs[32 * 130];   // [k][row 0..127], stride 130
  __shared__ __align__(16) ull  Wsd[32 * 67];    // [k][n 0..63] dup f32x2, stride 67
  __shared__ int toks[128];

  const int tid = threadIdx.x;
  const int r0 = blockIdx.x * 128;
  const int c0 = blockIdx.y * 64;

  if (tid < 128) {
    int r = r0 + tid;
    toks[tid] = x[(r & 63) * Tk + (r >> 6)];  // b = r&63, t = r>>6
  }
  __syncthreads();

  ull acc[4][4] = {};                 // 4 adjacent-row pairs x 4 cols
  const int l16 = tid & 15;
  const int n0 = (tid >> 4) * 4;
  const int f4 = tid & 7;             // fill: float4 index within 32-float chunk
  const int rw = tid >> 3;            // fill: base row 0..31

  for (int kc = 0; kc < Dk; kc += 32) {
#pragma unroll
    for (int i = 0; i < 4; i++) {
      int row = rw + i * 32;
      float4 v = *reinterpret_cast<const float4*>(
          &emb[(long)toks[row] * Dk + kc + f4 * 4]);
      Xs[(f4 * 4 + 0) * 130 + row] = v.x;
      Xs[(f4 * 4 + 1) * 130 + row] = v.y;
      Xs[(f4 * 4 + 2) * 130 + row] = v.z;
      Xs[(f4 * 4 + 3) * 130 + row] = v.w;
    }
#pragma unroll
    for (int i = 0; i < 2; i++) {
      int n = rw + i * 32;
      float4 v = *reinterpret_cast<const float4*>(
          &W_ih[(long)(c0 + n) * Dk + kc + f4 * 4]);
      Wsd[(f4 * 4 + 0) * 67 + n] = pack2(v.x, v.x);
      Wsd[(f4 * 4 + 1) * 67 + n] = pack2(v.y, v.y);
      Wsd[(f4 * 4 + 2) * 67 + n] = pack2(v.z, v.z);
      Wsd[(f4 * 4 + 3) * 67 + n] = pack2(v.w, v.w);
    }
    __syncthreads();

#pragma unroll
    for (int k = 0; k < 32; k++) {
      ull av[4];
#pragma unroll
      for (int i = 0; i < 4; i++)
        av[i] = *reinterpret_cast<const ull*>(&Xs[k * 130 + 2 * (l16 + 16 * i)]);
      const ull* bp = &Wsd[k * 67 + n0];
      ull bb[4];
      bb[0] = bp[0]; bb[1] = bp[1]; bb[2] = bp[2]; bb[3] = bp[3];
#pragma unroll
      for (int i = 0; i < 4; i++)
#pragma unroll
        for (int j = 0; j < 4; j++)
          acc[i][j] = ffma2(av[i], bb[j], acc[i][j]);
    }
    __syncthreads();
  }

  const float bs0 = b_ih[c0 + n0 + 0], bs1 = b_ih[c0 + n0 + 1];
  const float bs2 = b_ih[c0 + n0 + 2], bs3 = b_ih[c0 + n0 + 3];
#pragma unroll
  for (int i = 0; i < 4; i++) {
    float2 u0 = unpack2(acc[i][0]), u1 = unpack2(acc[i][1]);
    float2 u2 = unpack2(acc[i][2]), u3 = unpack2(acc[i][3]);
    long rowa = (long)(r0 + 2 * (l16 + 16 * i)) * Gk + c0 + n0;   // lo: row 2m
    float4 lo = make_float4(u0.x + bs0, u1.x + bs1, u2.x + bs2, u3.x + bs3);
    float4 hi = make_float4(u0.y + bs0, u1.y + bs1, u2.y + bs2, u3.y + bs3);
    *reinterpret_cast<float4*>(&g_gates[rowa]) = lo;
    *reinterpret_cast<float4*>(&g_gates[rowa + Gk]) = hi;          // hi: row 2m+1
  }
}

// ============================================================================
// init_bar: generation-relative atomic barrier (replay-safe). Used ONCE at
// kernel entry to publish the flag resets.
// ============================================================================
__device__ __forceinline__ void init_bar() {
  __threadfence();
  __syncthreads();
  if (threadIdx.x == 0) {
    unsigned my = g_bar_gen;
    if (atomicAdd(&g_bar_count, 1u) == NB - 1) {
      g_bar_count = 0;
      __threadfence();
      g_bar_gen = my + 1;
    } else {
      while (g_bar_gen == my) { }
      __threadfence();
    }
  }
  __syncthreads();
}

// ============================================================================
// Persistent GRU recurrence — producer/consumer dataflow, NO grid barrier.
//   Chunk (q,i) of the h(t-1) A-tile needs producers q*32+i*4+{0..3}. Only
//   threads q*64+{0..3} poll (one flag each); the per-chunk __syncthreads
//   propagates the acquire block-wide. Accumulation order bit-identical to
//   all passing versions.
// ============================================================================
__global__ __launch_bounds__(256, 1) void gru_persistent(
    const float* __restrict__ W_hh, const float* __restrict__ b_hh) {
  extern __shared__ float smem[];
  float* Ws    = smem;                 // [1024 k][24 rows]          96 KB
  float* HsBuf = smem + 24576;         // [2 buf][4 q][32 k][64 b]   64 KB
  float* P     = HsBuf + 16384;        // [4 s][64 b][26 pad]        26 KB
  float* Hprev = P + 6656;             // [64 b][8 jl]                2 KB

  const int tid = threadIdx.x;
  const int g = blockIdx.x;            // 0..127: h-cols g*8..g*8+7
  const int q = tid >> 6;              // k-quarter 0..3
  const int l = tid & 63;
  const int m0 = (l & 15) << 2;        // 4 batch rows
  const int n0 = (l >> 4) * 6;         // 6 local cols = 3 f32x2 pairs
  const int jl = tid & 7;              // gate-stage: local h-col
  const int b0 = tid >> 3;             // gate-stage: batch (and b0+32)
  const bool poller = (l < 4);         // 16 pollers: threads q*64+{0..3}

  // ---- reset dataflow flags (persist across graph replays), then publish
  if (g == 0 && tid < NB) st_release(&g_flags[tid], 0u);

  // ---- load W slice once: local row L = e*8+c  ->  W_hh row e*1024+g*8+c
  for (int i = tid; i < 24 * 256; i += 256) {
    int L = i >> 8;
    int f4 = i & 255;
    int e = L >> 3, c = L & 7;
    float4 v = *reinterpret_cast<const float4*>(
        &W_hh[(long)(e * Hk + g * 8 + c) * Hk + f4 * 4]);
    int kk = f4 * 4;
    Ws[(kk + 0) * 24 + L] = v.x;
    Ws[(kk + 1) * 24 + L] = v.y;
    Ws[(kk + 2) * 24 + L] = v.z;
    Ws[(kk + 3) * 24 + L] = v.w;
  }
  const float bh0 = b_hh[g * 8 + jl];
  const float bh1 = b_hh[Hk + g * 8 + jl];
  const float bh2 = b_hh[2 * Hk + g * 8 + jl];

  init_bar();   // flag resets visible everywhere before any producer publish
  __syncthreads();

  const uint32_t hsbuf_s = (uint32_t)__cvta_generic_to_shared(HsBuf);

  for (int t = 0; t < Tk; t++) {
    // ---- prefetch gx for this step's gate stage (hidden under the GEMM)
    float ga0, ga1, ga2, gb0, gb1, gb2;
    {
      const float* p0 = &g_gates[(long)(t * 64 + b0) * Gk + g * 8 + jl];
      ga0 = p0[0]; ga1 = p0[Hk]; ga2 = p0[2 * Hk];
      const float* p1 = &g_gates[(long)(t * 64 + b0 + 32) * Gk + g * 8 + jl];
      gb0 = p1[0]; gb1 = p1[Hk]; gb2 = p1[2 * Hk];
    }

    if (t > 0) {
      const float* src = g_hsT + (long)(t - 1) * (Hk * Bk) + q * 256 * 64;
      {  // prologue: 16 pollers acquire chunk-0 producers; sync propagates
        if (poller) wait_one(g_flags + q * 32 + (tid & 3), (unsigned)t);
        __syncthreads();
        uint32_t dst = hsbuf_s + (uint32_t)((0 * 4 + q) * 2048 + l * 4) * 4;
        const float* s0 = src + l * 4;
#pragma unroll
        for (int j = 0; j < 8; j++) cp16(dst + j * 1024, s0 + j * 256);
        cp_commit();
      }

      ull acc[4][3] = {};
#pragma unroll 1
      for (int i = 0; i < 8; i++) {
        cp_wait0();
        // 16 pollers acquire chunk i+1 producers before the common sync
        if (i < 7 && poller)
          wait_one(g_flags + q * 32 + (i + 1) * 4 + (tid & 3), (unsigned)t);
        __syncthreads();   // chunk i resident + prior GEMM done + acquire visible
        if (i < 7) {       // issue chunk i+1 into the other buffer
          int bf = (i + 1) & 1;
          uint32_t dst = hsbuf_s + (uint32_t)((bf * 4 + q) * 2048 + l * 4) * 4;
          const float* s1 = src + (i + 1) * 2048 + l * 4;
#pragma unroll
          for (int j = 0; j < 8; j++) cp16(dst + j * 1024, s1 + j * 256);
          cp_commit();
        }
        const float* A = HsBuf + ((i & 1) * 4 + q) * 2048;
        const float* Bw = Ws + (q * 256 + i * 32) * 24;
#pragma unroll
        for (int kk = 0; kk < 32; kk++) {
          float4 av = *reinterpret_cast<const float4*>(&A[kk * 64 + m0]);
          const float* wr = &Bw[kk * 24 + n0];
          ull w0 = *reinterpret_cast<const ull*>(wr);
          ull w1 = *reinterpret_cast<const ull*>(wr + 2);
          ull w2 = *reinterpret_cast<const ull*>(wr + 4);
          ull a0 = pack2(av.x, av.x), a1 = pack2(av.y, av.y);
          ull a2 = pack2(av.z, av.z), a3 = pack2(av.w, av.w);
          acc[0][0] = ffma2(a0, w0, acc[0][0]);
          acc[0][1] = ffma2(a0, w1, acc[0][1]);
          acc[0][2] = ffma2(a0, w2, acc[0][2]);
          acc[1][0] = ffma2(a1, w0, acc[1][0]);
          acc[1][1] = ffma2(a1, w1, acc[1][1]);
          acc[1][2] = ffma2(a1, w2, acc[1][2]);
          acc[2][0] = ffma2(a2, w0, acc[2][0]);
          acc[2][1] = ffma2(a2, w1, acc[2][1]);
          acc[2][2] = ffma2(a2, w2, acc[2][2]);
          acc[3][0] = ffma2(a3, w0, acc[3][0]);
          acc[3][1] = ffma2(a3, w1, acc[3][1]);
          acc[3][2] = ffma2(a3, w2, acc[3][2]);
        }
      }

      // ---- quarter partials -> smem (stride 26: bank-spread, 8B aligned)
#pragma unroll
      for (int m = 0; m < 4; m++) {
        int bb = m0 + m;
        float* pp = &P[(q * 64 + bb) * 26 + n0];
#pragma unroll
        for (int p = 0; p < 3; p++)
          *reinterpret_cast<float2*>(pp + 2 * p) = unpack2(acc[m][p]);
      }
      __syncthreads();
    }

    // ---- gate stage: 2 outputs per thread (b0, jl) and (b0+32, jl)
#pragma unroll
    for (int r2 = 0; r2 < 2; r2++) {
      int bb = b0 + r2 * 32;
      float gx0 = r2 ? gb0 : ga0;
      float gx1 = r2 ? gb1 : ga1;
      float gx2 = r2 ? gb2 : ga2;
      float hr = 0.0f, hz = 0.0f, hn = 0.0f;
      if (t > 0) {
#pragma unroll
        for (int s = 0; s < 4; s++) {   // left fold s=0..3: identical order
          const float* pp = &P[(s * 64 + bb) * 26];
          hr += pp[jl];
          hz += pp[8 + jl];
          hn += pp[16 + jl];
        }
      }
      float rr = sigmoidf_(gx0 + hr + bh0);
      float zz = sigmoidf_(gx1 + hz + bh1);
      float nn = tanhf(gx2 + rr * (hn + bh2));
      float hp = (t == 0) ? 0.0f : Hprev[bb * 8 + jl];
      float hnew = (1.0f - zz) * nn + zz * hp;
      Hprev[bb * 8 + jl] = hnew;                               // own slot
      g_hsT[(long)t * (Hk * Bk) + (g * 8 + jl) * 64 + bb] = hnew;
    }

    // ---- release-publish: h(t) for this block's 8 columns (cumulative over
    // the __syncthreads() happens-before from all 256 threads' stores)
    __syncthreads();
    if (tid == 0) st_release(&g_flags[g], (unsigned)(t + 1));
  }
}

// ============================================================================
// Kernel 4 (round-11 verbatim): logits = hs @ W_fc^T + b_fc; sigmoid; labels.
//   label = (computed fp32 proba > 0.5f) — matches reference rounding exactly.
// ============================================================================
__global__ __launch_bounds__(256) void fc_kernel(const float* __restrict__ W_fc,
                                                 const float* __restrict__ b_fc,
                                                 float* __restrict__ out,
                                                 int write_labels) {
  __shared__ __align__(16) float Hs[32][64];
  __shared__ __align__(16) float Ws[32][64];

  const int t = blockIdx.x;
  const int tid = threadIdx.x;
  const float* __restrict__ hbT = g_hsT + (long)t * (Hk * Bk);

  ull acc[2][4] = {};
  const int m0 = (tid & 15) * 4;
  const int n0 = (tid >> 4) * 4;
  const int kr = tid >> 4, f4i = tid & 15;

  for (int kc = 0; kc < Hk; kc += 32) {
#pragma unroll
    for (int u = 0; u < 2; u++) {
      int kk = kr + u * 16;
      float4 v = *reinterpret_cast<const float4*>(&hbT[(long)(kc + kk) * 64 + f4i * 4]);
      *reinterpret_cast<float4*>(&Hs[kk][f4i * 4]) = v;
    }
#pragma unroll
    for (int i = 0; i < 2; i++) {
      int n = (tid >> 3) + i * 32;         // warp-coalesced: 4 rows x 8 f4
      int f4 = tid & 7;
      float4 w = *reinterpret_cast<const float4*>(&W_fc[(long)n * Hk + kc + f4 * 4]);
      Ws[f4 * 4 + 0][n] = w.x; Ws[f4 * 4 + 1][n] = w.y;
      Ws[f4 * 4 + 2][n] = w.z; Ws[f4 * 4 + 3][n] = w.w;
    }
    __syncthreads();

#pragma unroll
    for (int k = 0; k < 32; k++) {
      const ull* ap = reinterpret_cast<const ull*>(&Hs[k][m0]);
      ull a0 = ap[0], a1 = ap[1];
      float4 bv = *reinterpret_cast<const float4*>(&Ws[k][n0]);
      ull bb[4];
      bb[0] = pack2(bv.x, bv.x); bb[1] = pack2(bv.y, bv.y);
      bb[2] = pack2(bv.z, bv.z); bb[3] = pack2(bv.w, bv.w);
#pragma unroll
      for (int j = 0; j < 4; j++) {
        acc[0][j] = ffma2(a0, bb[j], acc[0][j]);
        acc[1][j] = ffma2(a1, bb[j], acc[1][j]);
      }
    }
    __syncthreads();
  }

  const float bs0 = b_fc[n0 + 0], bs1 = b_fc[n0 + 1];
  const float bs2 = b_fc[n0 + 2], bs3 = b_fc[n0 + 3];
#pragma unroll
  for (int i = 0; i < 2; i++) {
    float2 u0 = unpack2(acc[i][0]), u1 = unpack2(acc[i][1]);
    float2 u2 = unpack2(acc[i][2]), u3 = unpack2(acc[i][3]);
    float lg[2][4] = {
        {u0.x + bs0, u1.x + bs1, u2.x + bs2, u3.x + bs3},
        {u0.y + bs0, u1.y + bs1, u2.y + bs2, u3.y + bs3}};
#pragma unroll
    for (int p = 0; p < 2; p++) {
      int b = m0 + 2 * i + p;
      long base = ((long)b * Tk + t) * Ok + n0;
      float4 pr = make_float4(sigmoidf_(lg[p][0]), sigmoidf_(lg[p][1]),
                              sigmoidf_(lg[p][2]), sigmoidf_(lg[p][3]));
      *reinterpret_cast<float4*>(&out[base]) = pr;
      if (write_labels) {
        float4 lb = make_float4(pr.x > 0.5f ? 1.0f : 0.0f,
                                pr.y > 0.5f ? 1.0f : 0.0f,
                                pr.z > 0.5f ? 1.0f : 0.0f,
                                pr.w > 0.5f ? 1.0f : 0.0f);
        *reinterpret_cast<float4*>(&out[(long)BT * Ok + base]) = lb;
      }
    }
  }
}

// ============================================================================
// Launch: graph-capturable (kernel launches only, deterministic, no allocs)
// ============================================================================
extern "C" void kernel_launch(void* const* d_in, const int* in_sizes, int n_in,
                              void* d_out, int out_size) {
  const int*   x    = (const int*)d_in[0];
  const float* emb  = (const float*)d_in[1];
  const float* W_ih = (const float*)d_in[2];
  const float* W_hh = (const float*)d_in[3];
  const float* b_ih = (const float*)d_in[4];
  const float* b_hh = (const float*)d_in[5];
  const float* W_fc = (const float*)d_in[6];
  const float* b_fc = (const float*)d_in[7];
  float* out = (float*)d_out;

  const int smem_bytes = (24576 + 16384 + 6656 + 512) * (int)sizeof(float); // 188 KB
  cudaFuncSetAttribute(gru_persistent,
                       cudaFuncAttributeMaxDynamicSharedMemorySize, smem_bytes);

  gates_kernel<<<dim3(128, 48), 256>>>(x, emb, W_ih, b_ih);
  gru_persistent<<<NB, 256, smem_bytes>>>(W_hh, b_hh);

  const int write_labels = (out_size >= 2 * BT * Ok) ? 1 : 0;
  fc_kernel<<<256, 256>>>(W_fc, b_fc, out, write_labels);
}

// round 15
// speedup vs baseline: 1.7036x; 1.3506x over previous
#include <cuda_runtime.h>
#include <math.h>
#include <stdint.h>

// Problem dims
#define Bk 64
#define Tk 256
#define Dk 512
#define Hk 1024
#define Gk 3072   // 3*H
#define Ok 64
#define BT 16384  // B*T

#define NB 128    // persistent blocks, one per 8 h-columns; all co-resident (1/SM)

typedef unsigned long long ull;

// -------- device scratch (no allocation allowed; __device__ globals are the workaround)
__device__ float g_gates[(long)BT * Gk];      // [T][B][3H]  (201 MB)
__device__ float g_hsT[(long)Tk * Hk * Bk];   // [t][k][b] transposed h (64 MB)

__device__ unsigned g_bar_count;              // init barrier: returns to 0 each use
__device__ volatile unsigned g_bar_gen;       // init barrier: monotonic (replay-safe)
__device__ volatile unsigned g_flags[NB];     // flag barrier: per-block step count
__device__ volatile unsigned g_rel;           // flag barrier: release word

// -------- packed f32x2 helpers (Blackwell FFMA2: 2x fp32 FMA throughput, exact fp32)
__device__ __forceinline__ ull ffma2(ull a, ull b, ull c) {
  ull d;
  asm("fma.rn.f32x2 %0, %1, %2, %3;" : "=l"(d) : "l"(a), "l"(b), "l"(c));
  return d;
}
__device__ __forceinline__ ull pack2(float lo, float hi) {
  ull d; asm("mov.b64 %0, {%1, %2};" : "=l"(d) : "f"(lo), "f"(hi)); return d;
}
__device__ __forceinline__ float2 unpack2(ull v) {
  float2 r; asm("mov.b64 {%0, %1}, %2;" : "=f"(r.x), "=f"(r.y) : "l"(v)); return r;
}
__device__ __forceinline__ float sigmoidf_(float x) { return 1.0f / (1.0f + expf(-x)); }

// -------- cp.async (LDGSTS via L2: .cg — no L1 staleness issues)
__device__ __forceinline__ void cp16(uint32_t dst, const float* src) {
  asm volatile("cp.async.cg.shared.global [%0], [%1], 16;" :: "r"(dst), "l"(src));
}
__device__ __forceinline__ void cp_commit() { asm volatile("cp.async.commit_group;"); }

// ============================================================================
// Kernel 1 (round-11 verbatim — measured best): gates_x = gather(emb,x)@W_ih^T
//   + b_ih. Tile 128x64x32, warp-coalesced fills, adjacent-row f32x2 pairing.
// ============================================================================
__global__ __launch_bounds__(256) void gates_kernel(
    const int* __restrict__ x, const float* __restrict__ emb,
    const float* __restrict__ W_ih, const float* __restrict__ b_ih) {
  __shared__ __align__(16) float Xs[32 * 130];   // [k][row 0..127], stride 130
  __shared__ __align__(16) ull  Wsd[32 * 67];    // [k][n 0..63] dup f32x2, stride 67
  __shared__ int toks[128];

  const int tid = threadIdx.x;
  const int r0 = blockIdx.x * 128;
  const int c0 = blockIdx.y * 64;

  if (tid < 128) {
    int r = r0 + tid;
    toks[tid] = x[(r & 63) * Tk + (r >> 6)];  // b = r&63, t = r>>6
  }
  __syncthreads();

  ull acc[4][4] = {};                 // 4 adjacent-row pairs x 4 cols
  const int l16 = tid & 15;
  const int n0 = (tid >> 4) * 4;
  const int f4 = tid & 7;             // fill: float4 index within 32-float chunk
  const int rw = tid >> 3;            // fill: base row 0..31

  for (int kc = 0; kc < Dk; kc += 32) {
#pragma unroll
    for (int i = 0; i < 4; i++) {
      int row = rw + i * 32;
      float4 v = *reinterpret_cast<const float4*>(
          &emb[(long)toks[row] * Dk + kc + f4 * 4]);
      Xs[(f4 * 4 + 0) * 130 + row] = v.x;
      Xs[(f4 * 4 + 1) * 130 + row] = v.y;
      Xs[(f4 * 4 + 2) * 130 + row] = v.z;
      Xs[(f4 * 4 + 3) * 130 + row] = v.w;
    }
#pragma unroll
    for (int i = 0; i < 2; i++) {
      int n = rw + i * 32;
      float4 v = *reinterpret_cast<const float4*>(
          &W_ih[(long)(c0 + n) * Dk + kc + f4 * 4]);
      Wsd[(f4 * 4 + 0) * 67 + n] = pack2(v.x, v.x);
      Wsd[(f4 * 4 + 1) * 67 + n] = pack2(v.y, v.y);
      Wsd[(f4 * 4 + 2) * 67 + n] = pack2(v.z, v.z);
      Wsd[(f4 * 4 + 3) * 67 + n] = pack2(v.w, v.w);
    }
    __syncthreads();

#pragma unroll
    for (int k = 0; k < 32; k++) {
      ull av[4];
#pragma unroll
      for (int i = 0; i < 4; i++)
        av[i] = *reinterpret_cast<const ull*>(&Xs[k * 130 + 2 * (l16 + 16 * i)]);
      const ull* bp = &Wsd[k * 67 + n0];
      ull bb[4];
      bb[0] = bp[0]; bb[1] = bp[1]; bb[2] = bp[2]; bb[3] = bp[3];
#pragma unroll
      for (int i = 0; i < 4; i++)
#pragma unroll
        for (int j = 0; j < 4; j++)
          acc[i][j] = ffma2(av[i], bb[j], acc[i][j]);
    }
    __syncthreads();
  }

  const float bs0 = b_ih[c0 + n0 + 0], bs1 = b_ih[c0 + n0 + 1];
  const float bs2 = b_ih[c0 + n0 + 2], bs3 = b_ih[c0 + n0 + 3];
#pragma unroll
  for (int i = 0; i < 4; i++) {
    float2 u0 = unpack2(acc[i][0]), u1 = unpack2(acc[i][1]);
    float2 u2 = unpack2(acc[i][2]), u3 = unpack2(acc[i][3]);
    long rowa = (long)(r0 + 2 * (l16 + 16 * i)) * Gk + c0 + n0;   // lo: row 2m
    float4 lo = make_float4(u0.x + bs0, u1.x + bs1, u2.x + bs2, u3.x + bs3);
    float4 hi = make_float4(u0.y + bs0, u1.y + bs1, u2.y + bs2, u3.y + bs3);
    *reinterpret_cast<float4*>(&g_gates[rowa]) = lo;
    *reinterpret_cast<float4*>(&g_gates[rowa + Gk]) = hi;          // hi: row 2m+1
  }
}

// ============================================================================
// Barriers (round-11 verbatim — measured 4686 us total). init_bar publishes
// the flag resets once; flag_bar does parallel STG arrivals + block-0 scan.
// ============================================================================
__device__ __forceinline__ void init_bar() {
  __threadfence();
  __syncthreads();
  if (threadIdx.x == 0) {
    unsigned my = g_bar_gen;
    if (atomicAdd(&g_bar_count, 1u) == NB - 1) {
      g_bar_count = 0;
      __threadfence();
      g_bar_gen = my + 1;
    } else {
      while (g_bar_gen == my) { }
      __threadfence();
    }
  }
  __syncthreads();
}

__device__ __forceinline__ void flag_bar(unsigned s) {
  __syncthreads();                      // all block threads' writes precede leader
  if (blockIdx.x == 0) {
    if (threadIdx.x == 0) { __threadfence(); g_flags[0] = s; }
    if (threadIdx.x < NB) { while (g_flags[threadIdx.x] < s) { } }
    __syncthreads();
    if (threadIdx.x == 0) { __threadfence(); g_rel = s; }
    __syncthreads();
  } else {
    if (threadIdx.x == 0) {
      __threadfence();
      g_flags[blockIdx.x] = s;
      while (g_rel < s) { }
      __threadfence();
    }
    __syncthreads();
  }
}

// ============================================================================
// Persistent GRU recurrence — round-11 structure (flag_bar once per step),
// with the cp.async fill pipeline deepened to 3 buffers: chunks are issued
// ~2 GEMM-chunks (~2500 cyc) before consumption, riding out the L2 burst when
// all 128 blocks fetch 32 KB simultaneously. Accumulation order bit-identical
// to all passing versions (4 k-quarter chains, smem left-fold s=0..3).
// ============================================================================
__global__ __launch_bounds__(256, 1) void gru_persistent(
    const float* __restrict__ W_hh, const float* __restrict__ b_hh) {
  extern __shared__ float smem[];
  float* Ws    = smem;                 // [1024 k][24 rows]          96 KB
  float* HsBuf = smem + 24576;         // [3 buf][4 q][32 k][64 b]   96 KB
  float* P     = HsBuf + 24576;        // [4 s][64 b][26 pad]        26 KB
  float* Hprev = P + 6656;             // [64 b][8 jl]                2 KB

  const int tid = threadIdx.x;
  const int g = blockIdx.x;            // 0..127: h-cols g*8..g*8+7
  const int q = tid >> 6;              // k-quarter 0..3
  const int l = tid & 63;
  const int m0 = (l & 15) << 2;        // 4 batch rows
  const int n0 = (l >> 4) * 6;         // 6 local cols = 3 f32x2 pairs
  const int jl = tid & 7;              // gate-stage: local h-col
  const int b0 = tid >> 3;             // gate-stage: batch (and b0+32)

  // ---- reset flag-barrier state (persists across graph replays), publish it
  if (g == 0) {
    if (tid < NB) g_flags[tid] = 0;
    if (tid == 0) g_rel = 0;
  }

  // ---- load W slice once: local row L = e*8+c  ->  W_hh row e*1024+g*8+c
  for (int i = tid; i < 24 * 256; i += 256) {
    int L = i >> 8;
    int f4 = i & 255;
    int e = L >> 3, c = L & 7;
    float4 v = *reinterpret_cast<const float4*>(
        &W_hh[(long)(e * Hk + g * 8 + c) * Hk + f4 * 4]);
    int kk = f4 * 4;
    Ws[(kk + 0) * 24 + L] = v.x;
    Ws[(kk + 1) * 24 + L] = v.y;
    Ws[(kk + 2) * 24 + L] = v.z;
    Ws[(kk + 3) * 24 + L] = v.w;
  }
  const float bh0 = b_hh[g * 8 + jl];
  const float bh1 = b_hh[Hk + g * 8 + jl];
  const float bh2 = b_hh[2 * Hk + g * 8 + jl];

  init_bar();   // flag resets visible everywhere before any flag_bar arrival
  __syncthreads();

  const uint32_t hsbuf_s = (uint32_t)__cvta_generic_to_shared(HsBuf);

  for (int t = 0; t < Tk; t++) {
    // ---- prefetch gx for this step's gate stage (hidden under the GEMM)
    float ga0, ga1, ga2, gb0, gb1, gb2;
    {
      const float* p0 = &g_gates[(long)(t * 64 + b0) * Gk + g * 8 + jl];
      ga0 = p0[0]; ga1 = p0[Hk]; ga2 = p0[2 * Hk];
      const float* p1 = &g_gates[(long)(t * 64 + b0 + 32) * Gk + g * 8 + jl];
      gb0 = p1[0]; gb1 = p1[Hk]; gb2 = p1[2 * Hk];
    }

    if (t > 0) {
      const float* src = g_hsT + (long)(t - 1) * (Hk * Bk) + q * 256 * 64;
      // prologue: issue chunks 0 and 1 into buffers 0 and 1
#pragma unroll
      for (int pc = 0; pc < 2; pc++) {
        uint32_t dst = hsbuf_s + (uint32_t)((pc * 4 + q) * 2048 + l * 4) * 4;
        const float* s0 = src + pc * 2048 + l * 4;
#pragma unroll
        for (int j = 0; j < 8; j++) cp16(dst + j * 1024, s0 + j * 256);
        cp_commit();
      }

      ull acc[4][3] = {};
      int cbuf = 0, nbuf = 2;
#pragma unroll 1
      for (int i = 0; i < 8; i++) {
        // chunk i resident: allow 1 in-flight group while a successor exists,
        // drain fully on the last chunk (wait_group 1 would under-wait it).
        if (i < 7) { asm volatile("cp.async.wait_group 1;" ::: "memory"); }
        else       { asm volatile("cp.async.wait_group 0;" ::: "memory"); }
        __syncthreads();   // chunk i visible block-wide; prior GEMM done
        if (i < 6) {       // issue chunk i+2 into the free buffer
          uint32_t dst = hsbuf_s + (uint32_t)((nbuf * 4 + q) * 2048 + l * 4) * 4;
          const float* s1 = src + (i + 2) * 2048 + l * 4;
#pragma unroll
          for (int j = 0; j < 8; j++) cp16(dst + j * 1024, s1 + j * 256);
          cp_commit();
          nbuf = (nbuf == 2) ? 0 : nbuf + 1;
        }
        const float* A = HsBuf + (cbuf * 4 + q) * 2048;
        cbuf = (cbuf == 2) ? 0 : cbuf + 1;
        const float* Bw = Ws + (q * 256 + i * 32) * 24;
#pragma unroll
        for (int kk = 0; kk < 32; kk++) {
          float4 av = *reinterpret_cast<const float4*>(&A[kk * 64 + m0]);
          const float* wr = &Bw[kk * 24 + n0];
          ull w0 = *reinterpret_cast<const ull*>(wr);
          ull w1 = *reinterpret_cast<const ull*>(wr + 2);
          ull w2 = *reinterpret_cast<const ull*>(wr + 4);
          ull a0 = pack2(av.x, av.x), a1 = pack2(av.y, av.y);
          ull a2 = pack2(av.z, av.z), a3 = pack2(av.w, av.w);
          acc[0][0] = ffma2(a0, w0, acc[0][0]);
          acc[0][1] = ffma2(a0, w1, acc[0][1]);
          acc[0][2] = ffma2(a0, w2, acc[0][2]);
          acc[1][0] = ffma2(a1, w0, acc[1][0]);
          acc[1][1] = ffma2(a1, w1, acc[1][1]);
          acc[1][2] = ffma2(a1, w2, acc[1][2]);
          acc[2][0] = ffma2(a2, w0, acc[2][0]);
          acc[2][1] = ffma2(a2, w1, acc[2][1]);
          acc[2][2] = ffma2(a2, w2, acc[2][2]);
          acc[3][0] = ffma2(a3, w0, acc[3][0]);
          acc[3][1] = ffma2(a3, w1, acc[3][1]);
          acc[3][2] = ffma2(a3, w2, acc[3][2]);
        }
      }

      // ---- quarter partials -> smem (stride 26: bank-spread, 8B aligned)
#pragma unroll
      for (int m = 0; m < 4; m++) {
        int bb = m0 + m;
        float* pp = &P[(q * 64 + bb) * 26 + n0];
#pragma unroll
        for (int p = 0; p < 3; p++)
          *reinterpret_cast<float2*>(pp + 2 * p) = unpack2(acc[m][p]);
      }
      __syncthreads();
    }

    // ---- gate stage: 2 outputs per thread (b0, jl) and (b0+32, jl)
#pragma unroll
    for (int r2 = 0; r2 < 2; r2++) {
      int bb = b0 + r2 * 32;
      float gx0 = r2 ? gb0 : ga0;
      float gx1 = r2 ? gb1 : ga1;
      float gx2 = r2 ? gb2 : ga2;
      float hr = 0.0f, hz = 0.0f, hn = 0.0f;
      if (t > 0) {
#pragma unroll
        for (int s = 0; s < 4; s++) {   // left fold s=0..3: identical order
          const float* pp = &P[(s * 64 + bb) * 26];
          hr += pp[jl];
          hz += pp[8 + jl];
          hn += pp[16 + jl];
        }
      }
      float rr = sigmoidf_(gx0 + hr + bh0);
      float zz = sigmoidf_(gx1 + hz + bh1);
      float nn = tanhf(gx2 + rr * (hn + bh2));
      float hp = (t == 0) ? 0.0f : Hprev[bb * 8 + jl];
      float hnew = (1.0f - zz) * nn + zz * hp;
      Hprev[bb * 8 + jl] = hnew;                               // own slot
      g_hsT[(long)t * (Hk * Bk) + (g * 8 + jl) * 64 + bb] = hnew;
    }

    flag_bar((unsigned)(t + 1));  // h(t) visible chip-wide; fences P reuse
  }
}

// ============================================================================
// Kernel 4 (round-11 verbatim): logits = hs @ W_fc^T + b_fc; sigmoid; labels.
//   label = (computed fp32 proba > 0.5f) — matches reference rounding exactly.
// ============================================================================
__global__ __launch_bounds__(256) void fc_kernel(const float* __restrict__ W_fc,
                                                 const float* __restrict__ b_fc,
                                                 float* __restrict__ out,
                                                 int write_labels) {
  __shared__ __align__(16) float Hs[32][64];
  __shared__ __align__(16) float Ws[32][64];

  const int t = blockIdx.x;
  const int tid = threadIdx.x;
  const float* __restrict__ hbT = g_hsT + (long)t * (Hk * Bk);

  ull acc[2][4] = {};
  const int m0 = (tid & 15) * 4;
  const int n0 = (tid >> 4) * 4;
  const int kr = tid >> 4, f4i = tid & 15;

  for (int kc = 0; kc < Hk; kc += 32) {
#pragma unroll
    for (int u = 0; u < 2; u++) {
      int kk = kr + u * 16;
      float4 v = *reinterpret_cast<const float4*>(&hbT[(long)(kc + kk) * 64 + f4i * 4]);
      *reinterpret_cast<float4*>(&Hs[kk][f4i * 4]) = v;
    }
#pragma unroll
    for (int i = 0; i < 2; i++) {
      int n = (tid >> 3) + i * 32;         // warp-coalesced: 4 rows x 8 f4
      int f4 = tid & 7;
      float4 w = *reinterpret_cast<const float4*>(&W_fc[(long)n * Hk + kc + f4 * 4]);
      Ws[f4 * 4 + 0][n] = w.x; Ws[f4 * 4 + 1][n] = w.y;
      Ws[f4 * 4 + 2][n] = w.z; Ws[f4 * 4 + 3][n] = w.w;
    }
    __syncthreads();

#pragma unroll
    for (int k = 0; k < 32; k++) {
      const ull* ap = reinterpret_cast<const ull*>(&Hs[k][m0]);
      ull a0 = ap[0], a1 = ap[1];
      float4 bv = *reinterpret_cast<const float4*>(&Ws[k][n0]);
      ull bb[4];
      bb[0] = pack2(bv.x, bv.x); bb[1] = pack2(bv.y, bv.y);
      bb[2] = pack2(bv.z, bv.z); bb[3] = pack2(bv.w, bv.w);
#pragma unroll
      for (int j = 0; j < 4; j++) {
        acc[0][j] = ffma2(a0, bb[j], acc[0][j]);
        acc[1][j] = ffma2(a1, bb[j], acc[1][j]);
      }
    }
    __syncthreads();
  }

  const float bs0 = b_fc[n0 + 0], bs1 = b_fc[n0 + 1];
  const float bs2 = b_fc[n0 + 2], bs3 = b_fc[n0 + 3];
#pragma unroll
  for (int i = 0; i < 2; i++) {
    float2 u0 = unpack2(acc[i][0]), u1 = unpack2(acc[i][1]);
    float2 u2 = unpack2(acc[i][2]), u3 = unpack2(acc[i][3]);
    float lg[2][4] = {
        {u0.x + bs0, u1.x + bs1, u2.x + bs2, u3.x + bs3},
        {u0.y + bs0, u1.y + bs1, u2.y + bs2, u3.y + bs3}};
#pragma unroll
    for (int p = 0; p < 2; p++) {
      int b = m0 + 2 * i + p;
      long base = ((long)b * Tk + t) * Ok + n0;
      float4 pr = make_float4(sigmoidf_(lg[p][0]), sigmoidf_(lg[p][1]),
                              sigmoidf_(lg[p][2]), sigmoidf_(lg[p][3]));
      *reinterpret_cast<float4*>(&out[base]) = pr;
      if (write_labels) {
        float4 lb = make_float4(pr.x > 0.5f ? 1.0f : 0.0f,
                                pr.y > 0.5f ? 1.0f : 0.0f,
                                pr.z > 0.5f ? 1.0f : 0.0f,
                                pr.w > 0.5f ? 1.0f : 0.0f);
        *reinterpret_cast<float4*>(&out[(long)BT * Ok + base]) = lb;
      }
    }
  }
}

// ============================================================================
// Launch: graph-capturable (kernel launches only, deterministic, no allocs)
// ============================================================================
extern "C" void kernel_launch(void* const* d_in, const int* in_sizes, int n_in,
                              void* d_out, int out_size) {
  const int*   x    = (const int*)d_in[0];
  const float* emb  = (const float*)d_in[1];
  const float* W_ih = (const float*)d_in[2];
  const float* W_hh = (const float*)d_in[3];
  const float* b_ih = (const float*)d_in[4];
  const float* b_hh = (const float*)d_in[5];
  const float* W_fc = (const float*)d_in[6];
  const float* b_fc = (const float*)d_in[7];
  float* out = (float*)d_out;

  // 96 KB W + 96 KB triple-buffered A + 26 KB P + 2 KB Hprev = 220 KB
  const int smem_bytes = (24576 + 24576 + 6656 + 512) * (int)sizeof(float);
  cudaFuncSetAttribute(gru_persistent,
                       cudaFuncAttributeMaxDynamicSharedMemorySize, smem_bytes);

  gates_kernel<<<dim3(128, 48), 256>>>(x, emb, W_ih, b_ih);
  gru_persistent<<<NB, 256, smem_bytes>>>(W_hh, b_hh);

  const int write_labels = (out_size >= 2 * BT * Ok) ? 1 : 0;
  fc_kernel<<<256, 256>>>(W_fc, b_fc, out, write_labels);
}